// round 2
// baseline (speedup 1.0000x reference)
#include <cuda_runtime.h>
#include <math.h>

// Problem constants
constexpr int B_ = 8;
constexpr int N_ = 2048;
constexpr int D_ = 512;
constexpr int M_ = B_ * N_;   // 16384 rows for QKV GEMM
constexpr float SCALE = 0.04419417382415922f; // 1/sqrt(512)

// Tiling
constexpr int BM = 128, BN = 128, BK = 16, TM = 8, TN = 8;

// Scratch (static __device__ arrays: allocation-guard safe)
__device__ float g_q[(size_t)B_ * N_ * D_];
__device__ float g_k[(size_t)B_ * N_ * D_];
__device__ float g_v[(size_t)B_ * N_ * D_];
__device__ float g_s[(size_t)B_ * N_ * N_];   // scores / attn probs, 134 MB

// ---------------------------------------------------------------------------
// event_lengths may arrive as int64 (as declared) or int32 (JAX x64-disabled
// demotion). Detect at runtime: genuine int64 lengths are in [1, N_]; an
// int32 pair (v0, v1>=1) read as int64 is >= 2^32. Deterministic.
// ---------------------------------------------------------------------------
__device__ __forceinline__ long long get_len(const void* lens, int b)
{
    const long long* p64 = (const long long*)lens;
    long long probe = p64[0];
    if (probe >= 1 && probe <= (long long)N_) return p64[b];      // true int64
    return (long long)((const int*)lens)[b];                      // int32 data
}

// ---------------------------------------------------------------------------
// Kernel 1: fused QKV projection.  C = A @ W^T + bias
// A = x [M_, D_], W = [D_, D_] row-major (out_feat, in_feat), grid.z selects q/k/v
// ---------------------------------------------------------------------------
__global__ __launch_bounds__(256) void qkv_kernel(
    const float* __restrict__ x,
    const float* __restrict__ Wq, const float* __restrict__ bq,
    const float* __restrict__ Wk, const float* __restrict__ bk,
    const float* __restrict__ Wv, const float* __restrict__ bv)
{
    const float* W; const float* bias; float* out;
    if (blockIdx.z == 0)      { W = Wq; bias = bq; out = g_q; }
    else if (blockIdx.z == 1) { W = Wk; bias = bk; out = g_k; }
    else                      { W = Wv; bias = bv; out = g_v; }

    const int m0 = blockIdx.y * BM;
    const int n0 = blockIdx.x * BN;

    __shared__ float As[BK][BM];
    __shared__ float Bs[BK][BN];

    float acc[TM][TN] = {};
    const int tid = threadIdx.x;
    const int tx = tid % 16, ty = tid / 16;

    for (int k0 = 0; k0 < D_; k0 += BK) {
        // A tile: 128 rows x 16 k  (x row-major [M_, D_])
        #pragma unroll
        for (int i = 0; i < 2; i++) {
            int f = tid + i * 256;
            int r = f >> 2;
            int c = (f & 3) * 4;
            float4 v = *(const float4*)(x + (size_t)(m0 + r) * D_ + k0 + c);
            As[c + 0][r] = v.x; As[c + 1][r] = v.y;
            As[c + 2][r] = v.z; As[c + 3][r] = v.w;
        }
        // B tile: W rows n0..n0+127, cols k0..k0+15
        #pragma unroll
        for (int i = 0; i < 2; i++) {
            int f = tid + i * 256;
            int r = f >> 2;
            int c = (f & 3) * 4;
            float4 v = *(const float4*)(W + (size_t)(n0 + r) * D_ + k0 + c);
            Bs[c + 0][r] = v.x; Bs[c + 1][r] = v.y;
            Bs[c + 2][r] = v.z; Bs[c + 3][r] = v.w;
        }
        __syncthreads();
        #pragma unroll
        for (int kk = 0; kk < BK; kk++) {
            float a[TM], b[TN];
            #pragma unroll
            for (int i = 0; i < TM; i++) a[i] = As[kk][ty * TM + i];
            #pragma unroll
            for (int j = 0; j < TN; j++) b[j] = Bs[kk][tx * TN + j];
            #pragma unroll
            for (int i = 0; i < TM; i++)
                #pragma unroll
                for (int j = 0; j < TN; j++)
                    acc[i][j] += a[i] * b[j];
        }
        __syncthreads();
    }

    #pragma unroll
    for (int i = 0; i < TM; i++) {
        int m = m0 + ty * TM + i;
        #pragma unroll
        for (int j = 0; j < TN; j++) {
            int n = n0 + tx * TN + j;
            out[(size_t)m * D_ + n] = acc[i][j] + bias[n];
        }
    }
}

// ---------------------------------------------------------------------------
// Kernel 2: scores.  S[b,i,j] = scale * (q[b,i,:] . k[b,j,:]), masked to -1e9
// ---------------------------------------------------------------------------
__global__ __launch_bounds__(256) void scores_kernel(
    const void* __restrict__ lens)
{
    const int b = blockIdx.z;
    const float* A = g_q + (size_t)b * N_ * D_;
    const float* Bm = g_k + (size_t)b * N_ * D_;
    float* C = g_s + (size_t)b * N_ * N_;
    const long long L = get_len(lens, b);

    const int m0 = blockIdx.y * BM;   // query rows
    const int n0 = blockIdx.x * BN;   // key cols

    __shared__ float As[BK][BM];
    __shared__ float Bs[BK][BN];

    float acc[TM][TN] = {};
    const int tid = threadIdx.x;
    const int tx = tid % 16, ty = tid / 16;

    for (int k0 = 0; k0 < D_; k0 += BK) {
        #pragma unroll
        for (int i = 0; i < 2; i++) {
            int f = tid + i * 256;
            int r = f >> 2;
            int c = (f & 3) * 4;
            float4 v = *(const float4*)(A + (size_t)(m0 + r) * D_ + k0 + c);
            As[c + 0][r] = v.x; As[c + 1][r] = v.y;
            As[c + 2][r] = v.z; As[c + 3][r] = v.w;
        }
        #pragma unroll
        for (int i = 0; i < 2; i++) {
            int f = tid + i * 256;
            int r = f >> 2;
            int c = (f & 3) * 4;
            float4 v = *(const float4*)(Bm + (size_t)(n0 + r) * D_ + k0 + c);
            Bs[c + 0][r] = v.x; Bs[c + 1][r] = v.y;
            Bs[c + 2][r] = v.z; Bs[c + 3][r] = v.w;
        }
        __syncthreads();
        #pragma unroll
        for (int kk = 0; kk < BK; kk++) {
            float a[TM], b[TN];
            #pragma unroll
            for (int i = 0; i < TM; i++) a[i] = As[kk][ty * TM + i];
            #pragma unroll
            for (int j = 0; j < TN; j++) b[j] = Bs[kk][tx * TN + j];
            #pragma unroll
            for (int i = 0; i < TM; i++)
                #pragma unroll
                for (int j = 0; j < TN; j++)
                    acc[i][j] += a[i] * b[j];
        }
        __syncthreads();
    }

    #pragma unroll
    for (int i = 0; i < TM; i++) {
        int qi = m0 + ty * TM + i;
        #pragma unroll
        for (int j = 0; j < TN; j++) {
            int kj = n0 + tx * TN + j;
            float v = acc[i][j] * SCALE;
            if (qi >= L || kj >= L) v = -1000000000.0f;
            C[(size_t)qi * N_ + kj] = v;
        }
    }
}

// ---------------------------------------------------------------------------
// Kernel 3: row softmax over g_s (in place).  One block per row, 256 threads.
// ---------------------------------------------------------------------------
__global__ __launch_bounds__(256) void softmax_kernel()
{
    const size_t row = blockIdx.x;
    float4* p4 = (float4*)(g_s + row * N_);
    const int tid = threadIdx.x;

    float4 v0 = p4[tid];
    float4 v1 = p4[tid + 256];

    float lmax = fmaxf(fmaxf(fmaxf(v0.x, v0.y), fmaxf(v0.z, v0.w)),
                       fmaxf(fmaxf(v1.x, v1.y), fmaxf(v1.z, v1.w)));

    __shared__ float smax[8];
    __shared__ float ssum[8];

    #pragma unroll
    for (int o = 16; o > 0; o >>= 1)
        lmax = fmaxf(lmax, __shfl_xor_sync(0xffffffffu, lmax, o));
    if ((tid & 31) == 0) smax[tid >> 5] = lmax;
    __syncthreads();
    float gmax = smax[0];
    #pragma unroll
    for (int i = 1; i < 8; i++) gmax = fmaxf(gmax, smax[i]);

    v0.x = __expf(v0.x - gmax); v0.y = __expf(v0.y - gmax);
    v0.z = __expf(v0.z - gmax); v0.w = __expf(v0.w - gmax);
    v1.x = __expf(v1.x - gmax); v1.y = __expf(v1.y - gmax);
    v1.z = __expf(v1.z - gmax); v1.w = __expf(v1.w - gmax);

    float lsum = v0.x + v0.y + v0.z + v0.w + v1.x + v1.y + v1.z + v1.w;
    #pragma unroll
    for (int o = 16; o > 0; o >>= 1)
        lsum += __shfl_xor_sync(0xffffffffu, lsum, o);
    if ((tid & 31) == 0) ssum[tid >> 5] = lsum;
    __syncthreads();
    float gsum = 0.f;
    #pragma unroll
    for (int i = 0; i < 8; i++) gsum += ssum[i];

    float inv = 1.0f / gsum;
    v0.x *= inv; v0.y *= inv; v0.z *= inv; v0.w *= inv;
    v1.x *= inv; v1.y *= inv; v1.z *= inv; v1.w *= inv;

    p4[tid] = v0;
    p4[tid + 256] = v1;
}

// ---------------------------------------------------------------------------
// Kernel 4: output.  O[b] = P[b] @ V[b]   (P: [N_,N_] row-major, V: [N_,D_])
// ---------------------------------------------------------------------------
__global__ __launch_bounds__(256) void out_kernel(float* __restrict__ Out)
{
    const int b = blockIdx.z;
    const float* A = g_s + (size_t)b * N_ * N_;   // [N_, N_]
    const float* Bm = g_v + (size_t)b * N_ * D_;  // [N_, D_]
    float* C = Out + (size_t)b * N_ * D_;

    const int m0 = blockIdx.y * BM;
    const int n0 = blockIdx.x * BN;

    __shared__ float As[BK][BM];
    __shared__ float Bs[BK][BN];

    float acc[TM][TN] = {};
    const int tid = threadIdx.x;
    const int tx = tid % 16, ty = tid / 16;

    for (int k0 = 0; k0 < N_; k0 += BK) {
        // A tile: 128 rows x 16 k  (A row-major [N_, N_])
        #pragma unroll
        for (int i = 0; i < 2; i++) {
            int f = tid + i * 256;
            int r = f >> 2;
            int c = (f & 3) * 4;
            float4 v = *(const float4*)(A + (size_t)(m0 + r) * N_ + k0 + c);
            As[c + 0][r] = v.x; As[c + 1][r] = v.y;
            As[c + 2][r] = v.z; As[c + 3][r] = v.w;
        }
        // B tile: 16 k-rows x 128 n-cols from row-major [N_, D_]
        #pragma unroll
        for (int i = 0; i < 2; i++) {
            int f = tid + i * 256;
            int r = f >> 5;          // 0..15
            int c = (f & 31) * 4;    // 0..124
            float4 v = *(const float4*)(Bm + (size_t)(k0 + r) * D_ + n0 + c);
            *(float4*)&Bs[r][c] = v;
        }
        __syncthreads();
        #pragma unroll
        for (int kk = 0; kk < BK; kk++) {
            float a[TM], bb[TN];
            #pragma unroll
            for (int i = 0; i < TM; i++) a[i] = As[kk][ty * TM + i];
            #pragma unroll
            for (int j = 0; j < TN; j++) bb[j] = Bs[kk][tx * TN + j];
            #pragma unroll
            for (int i = 0; i < TM; i++)
                #pragma unroll
                for (int j = 0; j < TN; j++)
                    acc[i][j] += a[i] * bb[j];
        }
        __syncthreads();
    }

    #pragma unroll
    for (int i = 0; i < TM; i++) {
        int m = m0 + ty * TM + i;
        #pragma unroll
        for (int j = 0; j < TN; j++) {
            int n = n0 + tx * TN + j;
            C[(size_t)m * D_ + n] = acc[i][j];
        }
    }
}

// ---------------------------------------------------------------------------
extern "C" void kernel_launch(void* const* d_in, const int* in_sizes, int n_in,
                              void* d_out, int out_size)
{
    const float* x    = (const float*)d_in[0];
    const void*  lens = d_in[1];
    const float* Wq   = (const float*)d_in[2];
    const float* bq   = (const float*)d_in[3];
    const float* Wk   = (const float*)d_in[4];
    const float* bk   = (const float*)d_in[5];
    const float* Wv   = (const float*)d_in[6];
    const float* bv   = (const float*)d_in[7];
    float* out = (float*)d_out;

    qkv_kernel<<<dim3(D_ / BN, M_ / BM, 3), 256>>>(x, Wq, bq, Wk, bk, Wv, bv);
    scores_kernel<<<dim3(N_ / BN, N_ / BM, B_), 256>>>(lens);
    softmax_kernel<<<B_ * N_, 256>>>();
    out_kernel<<<dim3(D_ / BN, N_ / BM, B_), 256>>>(out);
}

// round 4
// speedup vs baseline: 4.7028x; 4.7028x over previous
#include <cuda_runtime.h>
#include <cuda_bf16.h>
#include <cstdint>

// ---------------------------------------------------------------------------
// Problem constants
// ---------------------------------------------------------------------------
constexpr int B_ = 8;
constexpr int N_ = 2048;
constexpr int D_ = 512;
constexpr int M_ = B_ * N_;                    // 16384
constexpr float SCALE = 0.04419417382415922f;  // 1/sqrt(512)

// SMEM: 2 stages x (Ahi,Alo,Bhi,Blo each 128x64 bf16 = 16KB) = 128KB
constexpr int STAGE_BYTES = 65536;
constexpr int SMEM_BYTES = 2 * STAGE_BYTES;
constexpr int OFF_AL = 16384;
constexpr int OFF_BH = 32768;
constexpr int OFF_BL = 49152;

// ---------------------------------------------------------------------------
// Scratch (static __device__: allocation-guard safe)
// ---------------------------------------------------------------------------
__device__ __align__(256) __nv_bfloat16 g_xhi[(size_t)M_ * D_];
__device__ __align__(256) __nv_bfloat16 g_xlo[(size_t)M_ * D_];
__device__ __align__(256) __nv_bfloat16 g_whi[(size_t)3 * D_ * D_];
__device__ __align__(256) __nv_bfloat16 g_wlo[(size_t)3 * D_ * D_];
__device__ __align__(256) __nv_bfloat16 g_qhi[(size_t)M_ * D_];
__device__ __align__(256) __nv_bfloat16 g_qlo[(size_t)M_ * D_];
__device__ __align__(256) __nv_bfloat16 g_khi[(size_t)M_ * D_];
__device__ __align__(256) __nv_bfloat16 g_klo[(size_t)M_ * D_];
__device__ __align__(256) __nv_bfloat16 g_vthi[(size_t)B_ * D_ * N_];  // [b][d][n]
__device__ __align__(256) __nv_bfloat16 g_vtlo[(size_t)B_ * D_ * N_];
__device__ __align__(256) float         g_s[(size_t)B_ * N_ * N_];     // fp32 scores
__device__ __align__(256) __nv_bfloat16 g_phi[(size_t)B_ * N_ * N_];   // probs hi
__device__ __align__(256) __nv_bfloat16 g_plo[(size_t)B_ * N_ * N_];   // probs lo
__device__ __align__(256) float         g_mean[(size_t)B_ * D_];       // colmean(V)

// ---------------------------------------------------------------------------
// Helpers
// ---------------------------------------------------------------------------
__device__ __forceinline__ uint32_t smem_u32(const void* p) {
    uint32_t a;
    asm("{ .reg .u64 t; cvta.to.shared.u64 t, %1; cvt.u32.u64 %0, t; }" : "=r"(a) : "l"(p));
    return a;
}
#define SW128(o) ((o) ^ (((o) >> 3) & 0x70))

#define CP16(dst, src) \
    asm volatile("cp.async.cg.shared.global [%0], [%1], 16;" :: "r"(dst), "l"(src) : "memory")
#define CP_COMMIT() asm volatile("cp.async.commit_group;" ::: "memory")
#define CP_WAIT1() asm volatile("cp.async.wait_group 1;" ::: "memory")
#define CP_WAIT0() asm volatile("cp.async.wait_group 0;" ::: "memory")

#define LDSM4(r0, r1, r2, r3, a) \
    asm volatile("ldmatrix.sync.aligned.m8n8.x4.shared.b16 {%0,%1,%2,%3}, [%4];" \
                 : "=r"(r0), "=r"(r1), "=r"(r2), "=r"(r3) : "r"(a))

#define MMA(c, a, b0, b1) \
    asm volatile("mma.sync.aligned.m16n8k16.row.col.f32.bf16.bf16.f32 " \
                 "{%0,%1,%2,%3},{%4,%5,%6,%7},{%8,%9},{%0,%1,%2,%3};" \
                 : "+f"((c)[0]), "+f"((c)[1]), "+f"((c)[2]), "+f"((c)[3]) \
                 : "r"((a)[0]), "r"((a)[1]), "r"((a)[2]), "r"((a)[3]), "r"(b0), "r"(b1))

__device__ __forceinline__ void split2(float f, __nv_bfloat16& h, __nv_bfloat16& l) {
    h = __float2bfloat16_rn(f);
    l = __float2bfloat16_rn(f - __bfloat162float(h));
}

// event_lengths dtype sniffing (int64 vs int32-demoted)
__device__ __forceinline__ long long get_len(const void* lens, int b) {
    const long long* p64 = (const long long*)lens;
    long long probe = p64[0];
    if (probe >= 1 && probe <= (long long)N_) return p64[b];
    return (long long)((const int*)lens)[b];
}

// ---------------------------------------------------------------------------
// Async stage loader: 4 tiles of 128 rows x 64 bf16 (SW128) per stage
// ---------------------------------------------------------------------------
__device__ __forceinline__ void load_stage(
    const __nv_bfloat16* __restrict__ Ah, const __nv_bfloat16* __restrict__ Al, int lda,
    const __nv_bfloat16* __restrict__ Bh, const __nv_bfloat16* __restrict__ Bl, int ldb,
    int m0, int n0, int k0, uint32_t sbase, int tid)
{
    #pragma unroll
    for (int i = 0; i < 4; i++) {
        int idx = tid + i * 256;
        int r = idx >> 3;
        int c16 = idx & 7;
        uint32_t off = SW128((uint32_t)(r * 128 + c16 * 16));
        const __nv_bfloat16* a = Ah + (size_t)(m0 + r) * lda + k0 + c16 * 8;
        const __nv_bfloat16* al = Al + (size_t)(m0 + r) * lda + k0 + c16 * 8;
        const __nv_bfloat16* b = Bh + (size_t)(n0 + r) * ldb + k0 + c16 * 8;
        const __nv_bfloat16* bl = Bl + (size_t)(n0 + r) * ldb + k0 + c16 * 8;
        CP16(sbase + off, a);
        CP16(sbase + OFF_AL + off, al);
        CP16(sbase + OFF_BH + off, b);
        CP16(sbase + OFF_BL + off, bl);
    }
    CP_COMMIT();
}

// ---------------------------------------------------------------------------
// Compute one 64-wide K chunk from SMEM stage into acc (split-bf16, 3 products)
// ---------------------------------------------------------------------------
__device__ __forceinline__ void compute_chunk(uint32_t sb, int wm, int wn, int lane,
                                              float acc[4][4][4])
{
    const uint32_t rA = sb + (uint32_t)(wm * 64 + (lane & 15)) * 128;
    const uint32_t rB = sb + OFF_BH + (uint32_t)(wn * 32 + (lane & 15)) * 128;
    const uint32_t xr = (uint32_t)(lane & 7) << 4;
    const uint32_t half = (uint32_t)(lane >> 4) << 4;

    #pragma unroll
    for (int ks = 0; ks < 4; ks++) {
        uint32_t c = ((uint32_t)(ks * 32) + half) ^ xr;
        uint32_t ah[4][4], al[4][4], bh[4][2], bl[4][2];
        #pragma unroll
        for (int ma = 0; ma < 4; ma++) {
            LDSM4(ah[ma][0], ah[ma][1], ah[ma][2], ah[ma][3], rA + ma * 2048 + c);
            LDSM4(al[ma][0], al[ma][1], al[ma][2], al[ma][3], rA + OFF_AL + ma * 2048 + c);
        }
        #pragma unroll
        for (int p = 0; p < 2; p++) {
            uint32_t t0, t1, t2, t3;
            LDSM4(t0, t1, t2, t3, rB + p * 2048 + c);
            bh[p * 2][0] = t0; bh[p * 2 + 1][0] = t1;
            bh[p * 2][1] = t2; bh[p * 2 + 1][1] = t3;
            LDSM4(t0, t1, t2, t3, rB + 16384 + p * 2048 + c);
            bl[p * 2][0] = t0; bl[p * 2 + 1][0] = t1;
            bl[p * 2][1] = t2; bl[p * 2 + 1][1] = t3;
        }
        #pragma unroll
        for (int ma = 0; ma < 4; ma++)
            #pragma unroll
            for (int na = 0; na < 4; na++) {
                MMA(acc[ma][na], ah[ma], bh[na][0], bh[na][1]);
                MMA(acc[ma][na], ah[ma], bl[na][0], bl[na][1]);
                MMA(acc[ma][na], al[ma], bh[na][0], bh[na][1]);
            }
    }
}

// ---------------------------------------------------------------------------
// Full GEMM mainloop (C[128,128] += A[128,K] * B[128,K]^T), 2-stage pipeline
// ---------------------------------------------------------------------------
__device__ __forceinline__ void gemm_mainloop(
    const __nv_bfloat16* Ah, const __nv_bfloat16* Al, int lda,
    const __nv_bfloat16* Bh, const __nv_bfloat16* Bl, int ldb,
    int m0, int n0, int nChunks, uint32_t sb, int tid, float acc[4][4][4])
{
    const int lane = tid & 31, wid = tid >> 5;
    const int wm = wid & 1, wn = wid >> 1;

    load_stage(Ah, Al, lda, Bh, Bl, ldb, m0, n0, 0, sb, tid);
    for (int c = 0; c < nChunks; c++) {
        if (c + 1 < nChunks) {
            load_stage(Ah, Al, lda, Bh, Bl, ldb, m0, n0, (c + 1) * 64,
                       sb + ((c + 1) & 1) * STAGE_BYTES, tid);
            CP_WAIT1();
        } else {
            CP_WAIT0();
        }
        __syncthreads();
        compute_chunk(sb + (c & 1) * STAGE_BYTES, wm, wn, lane, acc);
        __syncthreads();
    }
}

// ---------------------------------------------------------------------------
// Convert kernels: fp32 -> (hi, lo) bf16
// ---------------------------------------------------------------------------
__global__ __launch_bounds__(256) void convert_x_kernel(const float* __restrict__ x) {
    size_t i = (size_t)blockIdx.x * 256 + threadIdx.x;
    float4 v = ((const float4*)x)[i];
    __nv_bfloat16 h0, l0, h1, l1, h2, l2, h3, l3;
    split2(v.x, h0, l0); split2(v.y, h1, l1);
    split2(v.z, h2, l2); split2(v.w, h3, l3);
    ((__nv_bfloat162*)g_xhi)[i * 2]     = __nv_bfloat162(h0, h1);
    ((__nv_bfloat162*)g_xhi)[i * 2 + 1] = __nv_bfloat162(h2, h3);
    ((__nv_bfloat162*)g_xlo)[i * 2]     = __nv_bfloat162(l0, l1);
    ((__nv_bfloat162*)g_xlo)[i * 2 + 1] = __nv_bfloat162(l2, l3);
}

__global__ __launch_bounds__(256) void convert_w_kernel(const float* __restrict__ Wq,
                                                        const float* __restrict__ Wk,
                                                        const float* __restrict__ Wv) {
    int z = blockIdx.z;
    const float* W = (z == 0) ? Wq : (z == 1) ? Wk : Wv;
    size_t i = (size_t)blockIdx.x * 256 + threadIdx.x;
    float4 v = ((const float4*)W)[i];
    __nv_bfloat16 h0, l0, h1, l1, h2, l2, h3, l3;
    split2(v.x, h0, l0); split2(v.y, h1, l1);
    split2(v.z, h2, l2); split2(v.w, h3, l3);
    size_t base = (size_t)z * (D_ * D_ / 2);
    ((__nv_bfloat162*)g_whi)[base + i * 2]     = __nv_bfloat162(h0, h1);
    ((__nv_bfloat162*)g_whi)[base + i * 2 + 1] = __nv_bfloat162(h2, h3);
    ((__nv_bfloat162*)g_wlo)[base + i * 2]     = __nv_bfloat162(l0, l1);
    ((__nv_bfloat162*)g_wlo)[base + i * 2 + 1] = __nv_bfloat162(l2, l3);
}

// ---------------------------------------------------------------------------
// QKV projection GEMM. z: 0=q, 1=k, 2=v (v written transposed)
// ---------------------------------------------------------------------------
__global__ __launch_bounds__(256, 1) void qkv_mma_kernel(const float* __restrict__ bq,
                                                         const float* __restrict__ bk,
                                                         const float* __restrict__ bv) {
    extern __shared__ char dyn[];
    uint32_t sb = smem_u32(dyn);
    const int tid = threadIdx.x, lane = tid & 31, wid = tid >> 5;
    const int wm = wid & 1, wn = wid >> 1;
    const int z = blockIdx.z;
    const int m0 = blockIdx.y * 128, n0 = blockIdx.x * 128;

    float acc[4][4][4] = {};
    const __nv_bfloat16* Bh = g_whi + (size_t)z * D_ * D_;
    const __nv_bfloat16* Bl = g_wlo + (size_t)z * D_ * D_;
    gemm_mainloop(g_xhi, g_xlo, D_, Bh, Bl, D_, m0, n0, D_ / 64, sb, tid, acc);

    const float* bias = (z == 0) ? bq : (z == 1) ? bk : bv;

    if (z < 2) {
        __nv_bfloat16* oh = (z == 0) ? g_qhi : g_khi;
        __nv_bfloat16* ol = (z == 0) ? g_qlo : g_klo;
        #pragma unroll
        for (int ma = 0; ma < 4; ma++) {
            int m = m0 + wm * 64 + ma * 16 + (lane >> 2);
            #pragma unroll
            for (int na = 0; na < 4; na++) {
                int n = n0 + wn * 32 + na * 8 + (lane & 3) * 2;
                float bv0 = __ldg(bias + n), bv1 = __ldg(bias + n + 1);
                __nv_bfloat16 h0, l0, h1, l1;
                split2(acc[ma][na][0] + bv0, h0, l0);
                split2(acc[ma][na][1] + bv1, h1, l1);
                *(__nv_bfloat162*)(oh + (size_t)m * D_ + n) = __nv_bfloat162(h0, h1);
                *(__nv_bfloat162*)(ol + (size_t)m * D_ + n) = __nv_bfloat162(l0, l1);
                split2(acc[ma][na][2] + bv0, h0, l0);
                split2(acc[ma][na][3] + bv1, h1, l1);
                *(__nv_bfloat162*)(oh + (size_t)(m + 8) * D_ + n) = __nv_bfloat162(h0, h1);
                *(__nv_bfloat162*)(ol + (size_t)(m + 8) * D_ + n) = __nv_bfloat162(l0, l1);
            }
        }
    } else {
        // V: stage fp32 tile in SMEM, write transposed [b][d][n]
        float* sf = (float*)dyn;   // 128 x 129 fp32 = 66048 B (stages done)
        #pragma unroll
        for (int ma = 0; ma < 4; ma++) {
            int r = wm * 64 + ma * 16 + (lane >> 2);
            #pragma unroll
            for (int na = 0; na < 4; na++) {
                int nl = wn * 32 + na * 8 + (lane & 3) * 2;
                float bv0 = __ldg(bias + n0 + nl), bv1 = __ldg(bias + n0 + nl + 1);
                sf[r * 129 + nl]           = acc[ma][na][0] + bv0;
                sf[r * 129 + nl + 1]       = acc[ma][na][1] + bv1;
                sf[(r + 8) * 129 + nl]     = acc[ma][na][2] + bv0;
                sf[(r + 8) * 129 + nl + 1] = acc[ma][na][3] + bv1;
            }
        }
        __syncthreads();
        int b = m0 >> 11;
        int mloc = m0 & 2047;
        int r = tid >> 1;               // local d index 0..127
        int c0 = (tid & 1) * 64;        // seq half
        __nv_bfloat16* oh = g_vthi + ((size_t)b * D_ + n0 + r) * N_ + mloc + c0;
        __nv_bfloat16* ol = g_vtlo + ((size_t)b * D_ + n0 + r) * N_ + mloc + c0;
        #pragma unroll
        for (int c = 0; c < 64; c += 2) {
            __nv_bfloat16 h0, l0, h1, l1;
            split2(sf[(c0 + c) * 129 + r], h0, l0);
            split2(sf[(c0 + c + 1) * 129 + r], h1, l1);
            *(__nv_bfloat162*)(oh + c) = __nv_bfloat162(h0, h1);
            *(__nv_bfloat162*)(ol + c) = __nv_bfloat162(l0, l1);
        }
    }
}

// ---------------------------------------------------------------------------
// colmean(V) per batch: mean[b][d] = (1/N) sum_n v[b][n][d]
// ---------------------------------------------------------------------------
__global__ __launch_bounds__(256) void colmean_kernel() {
    int gw = blockIdx.x * 8 + (threadIdx.x >> 5);   // 0 .. B_*D_-1
    int lane = threadIdx.x & 31;
    const __nv_bfloat162* ph = (const __nv_bfloat162*)(g_vthi + (size_t)gw * N_);
    const __nv_bfloat162* pl = (const __nv_bfloat162*)(g_vtlo + (size_t)gw * N_);
    float s = 0.f;
    for (int i = lane; i < N_ / 2; i += 32) {
        __nv_bfloat162 a = ph[i], b2 = pl[i];
        s += __bfloat162float(a.x) + __bfloat162float(a.y)
           + __bfloat162float(b2.x) + __bfloat162float(b2.y);
    }
    #pragma unroll
    for (int o = 16; o > 0; o >>= 1) s += __shfl_xor_sync(0xffffffffu, s, o);
    if (lane == 0) g_mean[gw] = s * (1.0f / N_);
}

// ---------------------------------------------------------------------------
// Scores GEMM (q.k^T), scale + mask, fp32 out; only live tiles
// ---------------------------------------------------------------------------
__global__ __launch_bounds__(256, 1) void scores_mma_kernel(const void* __restrict__ lens) {
    const int b = blockIdx.z;
    const long long L = get_len(lens, b);
    const int Lpad = ((int)L + 127) & ~127;
    const int m0 = blockIdx.y * 128, n0 = blockIdx.x * 128;
    if (m0 >= Lpad || n0 >= Lpad) return;

    extern __shared__ char dyn[];
    uint32_t sb = smem_u32(dyn);
    const int tid = threadIdx.x, lane = tid & 31, wid = tid >> 5;
    const int wm = wid & 1, wn = wid >> 1;

    float acc[4][4][4] = {};
    const size_t off = (size_t)b * N_ * D_;
    gemm_mainloop(g_qhi + off, g_qlo + off, D_, g_khi + off, g_klo + off, D_,
                  m0, n0, D_ / 64, sb, tid, acc);

    float* C = g_s + (size_t)b * N_ * N_;
    #pragma unroll
    for (int ma = 0; ma < 4; ma++) {
        int qi = m0 + wm * 64 + ma * 16 + (lane >> 2);
        #pragma unroll
        for (int na = 0; na < 4; na++) {
            int kj = n0 + wn * 32 + na * 8 + (lane & 3) * 2;
            #pragma unroll
            for (int h = 0; h < 2; h++) {
                int q = qi + h * 8;
                bool qd = (q >= L);
                float2 v;
                v.x = (qd || kj >= L)     ? -1e9f : acc[ma][na][h * 2]     * SCALE;
                v.y = (qd || kj + 1 >= L) ? -1e9f : acc[ma][na][h * 2 + 1] * SCALE;
                *(float2*)(C + (size_t)q * N_ + kj) = v;
            }
        }
    }
}

// ---------------------------------------------------------------------------
// Row softmax over [0, Lpad), write split-bf16 probs (live rows only)
// ---------------------------------------------------------------------------
__global__ __launch_bounds__(256) void softmax_kernel(const void* __restrict__ lens) {
    const int b = blockIdx.y, qi = blockIdx.x;
    const long long L = get_len(lens, b);
    if (qi >= L) return;
    const int Lpad = ((int)L + 127) & ~127;
    const size_t rowoff = ((size_t)b * N_ + qi) * N_;
    const float4* p4 = (const float4*)(g_s + rowoff);
    const int tid = threadIdx.x;

    const bool h0 = tid * 4 < Lpad;
    const bool h1 = tid * 4 + 1024 < Lpad;
    float4 v0 = make_float4(-1e30f, -1e30f, -1e30f, -1e30f), v1 = v0;
    if (h0) v0 = p4[tid];
    if (h1) v1 = p4[tid + 256];

    float lmax = fmaxf(fmaxf(fmaxf(v0.x, v0.y), fmaxf(v0.z, v0.w)),
                       fmaxf(fmaxf(v1.x, v1.y), fmaxf(v1.z, v1.w)));
    __shared__ float smax[8], ssum[8];
    #pragma unroll
    for (int o = 16; o > 0; o >>= 1)
        lmax = fmaxf(lmax, __shfl_xor_sync(0xffffffffu, lmax, o));
    if ((tid & 31) == 0) smax[tid >> 5] = lmax;
    __syncthreads();
    float gmax = smax[0];
    #pragma unroll
    for (int i = 1; i < 8; i++) gmax = fmaxf(gmax, smax[i]);

    v0.x = __expf(v0.x - gmax); v0.y = __expf(v0.y - gmax);
    v0.z = __expf(v0.z - gmax); v0.w = __expf(v0.w - gmax);
    v1.x = __expf(v1.x - gmax); v1.y = __expf(v1.y - gmax);
    v1.z = __expf(v1.z - gmax); v1.w = __expf(v1.w - gmax);

    float lsum = v0.x + v0.y + v0.z + v0.w + v1.x + v1.y + v1.z + v1.w;
    #pragma unroll
    for (int o = 16; o > 0; o >>= 1)
        lsum += __shfl_xor_sync(0xffffffffu, lsum, o);
    if ((tid & 31) == 0) ssum[tid >> 5] = lsum;
    __syncthreads();
    float gsum = 0.f;
    #pragma unroll
    for (int i = 0; i < 8; i++) gsum += ssum[i];

    const float inv = 1.0f / gsum;
    __nv_bfloat16 h, l, h2, l2;
    if (h0) {
        size_t c = rowoff + tid * 4;
        split2(v0.x * inv, h, l); split2(v0.y * inv, h2, l2);
        *(__nv_bfloat162*)(g_phi + c)     = __nv_bfloat162(h, h2);
        *(__nv_bfloat162*)(g_plo + c)     = __nv_bfloat162(l, l2);
        split2(v0.z * inv, h, l); split2(v0.w * inv, h2, l2);
        *(__nv_bfloat162*)(g_phi + c + 2) = __nv_bfloat162(h, h2);
        *(__nv_bfloat162*)(g_plo + c + 2) = __nv_bfloat162(l, l2);
    }
    if (h1) {
        size_t c = rowoff + tid * 4 + 1024;
        split2(v1.x * inv, h, l); split2(v1.y * inv, h2, l2);
        *(__nv_bfloat162*)(g_phi + c)     = __nv_bfloat162(h, h2);
        *(__nv_bfloat162*)(g_plo + c)     = __nv_bfloat162(l, l2);
        split2(v1.z * inv, h, l); split2(v1.w * inv, h2, l2);
        *(__nv_bfloat162*)(g_phi + c + 2) = __nv_bfloat162(h, h2);
        *(__nv_bfloat162*)(g_plo + c + 2) = __nv_bfloat162(l, l2);
    }
}

// ---------------------------------------------------------------------------
// Output GEMM: O[b, 0:Lpad] = P[b, 0:Lpad, 0:Lpad] @ V[b, 0:Lpad]
// ---------------------------------------------------------------------------
__global__ __launch_bounds__(256, 1) void out_mma_kernel(float* __restrict__ Out,
                                                         const void* __restrict__ lens) {
    const int b = blockIdx.z;
    const long long L = get_len(lens, b);
    const int Lpad = ((int)L + 127) & ~127;
    const int m0 = blockIdx.y * 128, n0 = blockIdx.x * 128;
    if (m0 >= Lpad) return;

    extern __shared__ char dyn[];
    uint32_t sb = smem_u32(dyn);
    const int tid = threadIdx.x, lane = tid & 31, wid = tid >> 5;
    const int wm = wid & 1, wn = wid >> 1;

    float acc[4][4][4] = {};
    const size_t poff = (size_t)b * N_ * N_;
    const size_t voff = (size_t)b * D_ * N_;
    gemm_mainloop(g_phi + poff, g_plo + poff, N_, g_vthi + voff, g_vtlo + voff, N_,
                  m0, n0, Lpad / 64, sb, tid, acc);

    #pragma unroll
    for (int ma = 0; ma < 4; ma++) {
        int m = m0 + wm * 64 + ma * 16 + (lane >> 2);
        float* r0 = Out + ((size_t)b * N_ + m) * D_;
        float* r1 = Out + ((size_t)b * N_ + m + 8) * D_;
        #pragma unroll
        for (int na = 0; na < 4; na++) {
            int n = n0 + wn * 32 + na * 8 + (lane & 3) * 2;
            *(float2*)(r0 + n) = make_float2(acc[ma][na][0], acc[ma][na][1]);
            *(float2*)(r1 + n) = make_float2(acc[ma][na][2], acc[ma][na][3]);
        }
    }
}

// ---------------------------------------------------------------------------
// Fill dead rows: O[b, qi>=L, :] = colmean(V)
// ---------------------------------------------------------------------------
__global__ __launch_bounds__(128) void fill_kernel(float* __restrict__ Out,
                                                   const void* __restrict__ lens) {
    const int b = blockIdx.y, qi = blockIdx.x;
    const long long L = get_len(lens, b);
    if (qi < L) return;
    float4 v = ((const float4*)(g_mean + (size_t)b * D_))[threadIdx.x];
    ((float4*)(Out + ((size_t)b * N_ + qi) * D_))[threadIdx.x] = v;
}

// ---------------------------------------------------------------------------
extern "C" void kernel_launch(void* const* d_in, const int* in_sizes, int n_in,
                              void* d_out, int out_size)
{
    const float* x    = (const float*)d_in[0];
    const void*  lens = d_in[1];
    const float* Wq   = (const float*)d_in[2];
    const float* bq   = (const float*)d_in[3];
    const float* Wk   = (const float*)d_in[4];
    const float* bk   = (const float*)d_in[5];
    const float* Wv   = (const float*)d_in[6];
    const float* bv   = (const float*)d_in[7];
    float* out = (float*)d_out;

    cudaFuncSetAttribute(qkv_mma_kernel,    cudaFuncAttributeMaxDynamicSharedMemorySize, SMEM_BYTES);
    cudaFuncSetAttribute(scores_mma_kernel, cudaFuncAttributeMaxDynamicSharedMemorySize, SMEM_BYTES);
    cudaFuncSetAttribute(out_mma_kernel,    cudaFuncAttributeMaxDynamicSharedMemorySize, SMEM_BYTES);

    convert_x_kernel<<<M_ * D_ / 4 / 256, 256>>>(x);
    convert_w_kernel<<<dim3(D_ * D_ / 4 / 256, 1, 3), 256>>>(Wq, Wk, Wv);
    qkv_mma_kernel<<<dim3(D_ / 128, M_ / 128, 3), 256, SMEM_BYTES>>>(bq, bk, bv);
    colmean_kernel<<<B_ * D_ / 8, 256>>>();
    scores_mma_kernel<<<dim3(N_ / 128, N_ / 128, B_), 256, SMEM_BYTES>>>(lens);
    softmax_kernel<<<dim3(N_, B_), 256>>>(lens);
    out_mma_kernel<<<dim3(D_ / 128, N_ / 128, B_), 256, SMEM_BYTES>>>(out, lens);
    fill_kernel<<<dim3(N_, B_), 128>>>(out, lens);
}

// round 5
// speedup vs baseline: 5.6207x; 1.1952x over previous
#include <cuda_runtime.h>
#include <cuda_bf16.h>
#include <cstdint>

// ---------------------------------------------------------------------------
// Problem constants
// ---------------------------------------------------------------------------
constexpr int B_ = 8;
constexpr int N_ = 2048;
constexpr int D_ = 512;
constexpr int M_ = B_ * N_;                    // 16384
constexpr float SCALE = 0.04419417382415922f;  // 1/sqrt(512)

// SMEM: 3 stages x (Ahi,Alo,Bhi,Blo each 128x64 bf16 = 16KB) = 192KB
constexpr int STAGE_BYTES = 65536;
constexpr int NSTAGES = 3;
constexpr int SMEM_BYTES = NSTAGES * STAGE_BYTES;
constexpr int OFF_AL = 16384;
constexpr int OFF_BH = 32768;
constexpr int OFF_BL = 49152;

// ---------------------------------------------------------------------------
// Scratch (static __device__: allocation-guard safe)
// ---------------------------------------------------------------------------
__device__ __align__(256) __nv_bfloat16 g_xhi[(size_t)M_ * D_];
__device__ __align__(256) __nv_bfloat16 g_xlo[(size_t)M_ * D_];
__device__ __align__(256) __nv_bfloat16 g_whi[(size_t)3 * D_ * D_];
__device__ __align__(256) __nv_bfloat16 g_wlo[(size_t)3 * D_ * D_];
__device__ __align__(256) __nv_bfloat16 g_qhi[(size_t)M_ * D_];
__device__ __align__(256) __nv_bfloat16 g_qlo[(size_t)M_ * D_];
__device__ __align__(256) __nv_bfloat16 g_khi[(size_t)M_ * D_];
__device__ __align__(256) __nv_bfloat16 g_klo[(size_t)M_ * D_];
__device__ __align__(256) __nv_bfloat16 g_vthi[(size_t)B_ * D_ * N_];  // [b][d][n]
__device__ __align__(256) __nv_bfloat16 g_vtlo[(size_t)B_ * D_ * N_];
__device__ __align__(256) __nv_bfloat16 g_phi[(size_t)B_ * N_ * N_];   // exp numerators hi
__device__ __align__(256) __nv_bfloat16 g_plo[(size_t)B_ * N_ * N_];   // exp numerators lo
__device__ __align__(256) float         g_psum[(size_t)B_ * 16 * N_];  // per-tile row sums
__device__ __align__(256) float         g_rinv[(size_t)B_ * N_];       // 1/rowsum
__device__ __align__(256) float         g_mean[(size_t)B_ * D_];       // colmean(V)

// ---------------------------------------------------------------------------
// Helpers
// ---------------------------------------------------------------------------
__device__ __forceinline__ uint32_t smem_u32(const void* p) {
    uint32_t a;
    asm("{ .reg .u64 t; cvta.to.shared.u64 t, %1; cvt.u32.u64 %0, t; }" : "=r"(a) : "l"(p));
    return a;
}
#define SW128(o) ((o) ^ (((o) >> 3) & 0x70))

#define CP16(dst, src) \
    asm volatile("cp.async.cg.shared.global [%0], [%1], 16;" :: "r"(dst), "l"(src) : "memory")
#define CP_COMMIT() asm volatile("cp.async.commit_group;" ::: "memory")
#define CP_WAIT2() asm volatile("cp.async.wait_group 2;" ::: "memory")
#define CP_WAIT1() asm volatile("cp.async.wait_group 1;" ::: "memory")
#define CP_WAIT0() asm volatile("cp.async.wait_group 0;" ::: "memory")

#define LDSM4(r0, r1, r2, r3, a) \
    asm volatile("ldmatrix.sync.aligned.m8n8.x4.shared.b16 {%0,%1,%2,%3}, [%4];" \
                 : "=r"(r0), "=r"(r1), "=r"(r2), "=r"(r3) : "r"(a))

#define MMA(c, a, b0, b1) \
    asm volatile("mma.sync.aligned.m16n8k16.row.col.f32.bf16.bf16.f32 " \
                 "{%0,%1,%2,%3},{%4,%5,%6,%7},{%8,%9},{%0,%1,%2,%3};" \
                 : "+f"((c)[0]), "+f"((c)[1]), "+f"((c)[2]), "+f"((c)[3]) \
                 : "r"((a)[0]), "r"((a)[1]), "r"((a)[2]), "r"((a)[3]), "r"(b0), "r"(b1))

__device__ __forceinline__ void split2(float f, __nv_bfloat16& h, __nv_bfloat16& l) {
    h = __float2bfloat16_rn(f);
    l = __float2bfloat16_rn(f - __bfloat162float(h));
}

// event_lengths dtype sniffing (int64 vs int32-demoted)
__device__ __forceinline__ long long get_len(const void* lens, int b) {
    const long long* p64 = (const long long*)lens;
    long long probe = p64[0];
    if (probe >= 1 && probe <= (long long)N_) return p64[b];
    return (long long)((const int*)lens)[b];
}

// ---------------------------------------------------------------------------
// Async stage loader: 4 tiles of 128 rows x 64 bf16 (SW128) per stage
// ---------------------------------------------------------------------------
__device__ __forceinline__ void load_stage(
    const __nv_bfloat16* __restrict__ Ah, const __nv_bfloat16* __restrict__ Al, int lda,
    const __nv_bfloat16* __restrict__ Bh, const __nv_bfloat16* __restrict__ Bl, int ldb,
    int m0, int n0, int k0, uint32_t sbase, int tid)
{
    #pragma unroll
    for (int i = 0; i < 4; i++) {
        int idx = tid + i * 256;
        int r = idx >> 3;
        int c16 = idx & 7;
        uint32_t off = SW128((uint32_t)(r * 128 + c16 * 16));
        const __nv_bfloat16* a  = Ah + (size_t)(m0 + r) * lda + k0 + c16 * 8;
        const __nv_bfloat16* al = Al + (size_t)(m0 + r) * lda + k0 + c16 * 8;
        const __nv_bfloat16* b  = Bh + (size_t)(n0 + r) * ldb + k0 + c16 * 8;
        const __nv_bfloat16* bl = Bl + (size_t)(n0 + r) * ldb + k0 + c16 * 8;
        CP16(sbase + off, a);
        CP16(sbase + OFF_AL + off, al);
        CP16(sbase + OFF_BH + off, b);
        CP16(sbase + OFF_BL + off, bl);
    }
    CP_COMMIT();
}

// ---------------------------------------------------------------------------
// Compute one 64-wide K chunk from SMEM stage into acc (split-bf16, 3 products)
// ---------------------------------------------------------------------------
__device__ __forceinline__ void compute_chunk(uint32_t sb, int wm, int wn, int lane,
                                              float acc[4][4][4])
{
    const uint32_t rA = sb + (uint32_t)(wm * 64 + (lane & 15)) * 128;
    const uint32_t rB = sb + OFF_BH + (uint32_t)(wn * 32 + (lane & 15)) * 128;
    const uint32_t xr = (uint32_t)(lane & 7) << 4;
    const uint32_t half = (uint32_t)(lane >> 4) << 4;

    #pragma unroll
    for (int ks = 0; ks < 4; ks++) {
        uint32_t c = ((uint32_t)(ks * 32) + half) ^ xr;
        uint32_t ah[4][4], al[4][4], bh[4][2], bl[4][2];
        #pragma unroll
        for (int ma = 0; ma < 4; ma++) {
            LDSM4(ah[ma][0], ah[ma][1], ah[ma][2], ah[ma][3], rA + ma * 2048 + c);
            LDSM4(al[ma][0], al[ma][1], al[ma][2], al[ma][3], rA + OFF_AL + ma * 2048 + c);
        }
        #pragma unroll
        for (int p = 0; p < 2; p++) {
            uint32_t t0, t1, t2, t3;
            LDSM4(t0, t1, t2, t3, rB + p * 2048 + c);
            bh[p * 2][0] = t0; bh[p * 2 + 1][0] = t1;
            bh[p * 2][1] = t2; bh[p * 2 + 1][1] = t3;
            LDSM4(t0, t1, t2, t3, rB + 16384 + p * 2048 + c);
            bl[p * 2][0] = t0; bl[p * 2 + 1][0] = t1;
            bl[p * 2][1] = t2; bl[p * 2 + 1][1] = t3;
        }
        #pragma unroll
        for (int ma = 0; ma < 4; ma++)
            #pragma unroll
            for (int na = 0; na < 4; na++) {
                MMA(acc[ma][na], ah[ma], bh[na][0], bh[na][1]);
                MMA(acc[ma][na], ah[ma], bl[na][0], bl[na][1]);
                MMA(acc[ma][na], al[ma], bh[na][0], bh[na][1]);
            }
    }
}

// ---------------------------------------------------------------------------
// Full GEMM mainloop, 3-stage cp.async pipeline
// ---------------------------------------------------------------------------
__device__ __forceinline__ void gemm_mainloop(
    const __nv_bfloat16* Ah, const __nv_bfloat16* Al, int lda,
    const __nv_bfloat16* Bh, const __nv_bfloat16* Bl, int ldb,
    int m0, int n0, int nChunks, uint32_t sb, int tid, float acc[4][4][4])
{
    const int lane = tid & 31, wid = tid >> 5;
    const int wm = wid & 1, wn = wid >> 1;

    load_stage(Ah, Al, lda, Bh, Bl, ldb, m0, n0, 0, sb, tid);
    if (nChunks > 1)
        load_stage(Ah, Al, lda, Bh, Bl, ldb, m0, n0, 64, sb + STAGE_BYTES, tid);
    for (int c = 0; c < nChunks; c++) {
        if (c + 2 < nChunks) {
            load_stage(Ah, Al, lda, Bh, Bl, ldb, m0, n0, (c + 2) * 64,
                       sb + ((c + 2) % NSTAGES) * STAGE_BYTES, tid);
            CP_WAIT2();
        } else if (c + 1 < nChunks) {
            CP_WAIT1();
        } else {
            CP_WAIT0();
        }
        __syncthreads();
        compute_chunk(sb + (c % NSTAGES) * STAGE_BYTES, wm, wn, lane, acc);
        __syncthreads();
    }
}

// ---------------------------------------------------------------------------
// Convert kernels: fp32 -> (hi, lo) bf16
// ---------------------------------------------------------------------------
__global__ __launch_bounds__(256) void convert_x_kernel(const float* __restrict__ x) {
    size_t i = (size_t)blockIdx.x * 256 + threadIdx.x;
    float4 v = ((const float4*)x)[i];
    __nv_bfloat16 h0, l0, h1, l1, h2, l2, h3, l3;
    split2(v.x, h0, l0); split2(v.y, h1, l1);
    split2(v.z, h2, l2); split2(v.w, h3, l3);
    ((__nv_bfloat162*)g_xhi)[i * 2]     = __nv_bfloat162(h0, h1);
    ((__nv_bfloat162*)g_xhi)[i * 2 + 1] = __nv_bfloat162(h2, h3);
    ((__nv_bfloat162*)g_xlo)[i * 2]     = __nv_bfloat162(l0, l1);
    ((__nv_bfloat162*)g_xlo)[i * 2 + 1] = __nv_bfloat162(l2, l3);
}

__global__ __launch_bounds__(256) void convert_w_kernel(const float* __restrict__ Wq,
                                                        const float* __restrict__ Wk,
                                                        const float* __restrict__ Wv) {
    int z = blockIdx.z;
    const float* W = (z == 0) ? Wq : (z == 1) ? Wk : Wv;
    size_t i = (size_t)blockIdx.x * 256 + threadIdx.x;
    float4 v = ((const float4*)W)[i];
    __nv_bfloat16 h0, l0, h1, l1, h2, l2, h3, l3;
    split2(v.x, h0, l0); split2(v.y, h1, l1);
    split2(v.z, h2, l2); split2(v.w, h3, l3);
    size_t base = (size_t)z * (D_ * D_ / 2);
    ((__nv_bfloat162*)g_whi)[base + i * 2]     = __nv_bfloat162(h0, h1);
    ((__nv_bfloat162*)g_whi)[base + i * 2 + 1] = __nv_bfloat162(h2, h3);
    ((__nv_bfloat162*)g_wlo)[base + i * 2]     = __nv_bfloat162(l0, l1);
    ((__nv_bfloat162*)g_wlo)[base + i * 2 + 1] = __nv_bfloat162(l2, l3);
}

// ---------------------------------------------------------------------------
// QKV projection GEMM. z: 0=q, 1=k, 2=v (v written transposed)
// Dead rows (>= Lpad) skipped for q and k (never read downstream).
// ---------------------------------------------------------------------------
__global__ __launch_bounds__(256, 1) void qkv_mma_kernel(const float* __restrict__ bq,
                                                         const float* __restrict__ bk,
                                                         const float* __restrict__ bv,
                                                         const void* __restrict__ lens) {
    extern __shared__ char dyn[];
    uint32_t sb = smem_u32(dyn);
    const int tid = threadIdx.x, lane = tid & 31, wid = tid >> 5;
    const int wm = wid & 1, wn = wid >> 1;
    const int z = blockIdx.z;
    const int m0 = blockIdx.y * 128, n0 = blockIdx.x * 128;

    if (z < 2) {
        const long long L = get_len(lens, m0 >> 11);
        const int Lpad = ((int)L + 127) & ~127;
        if ((m0 & 2047) >= Lpad) return;
    }

    float acc[4][4][4] = {};
    const __nv_bfloat16* Bh = g_whi + (size_t)z * D_ * D_;
    const __nv_bfloat16* Bl = g_wlo + (size_t)z * D_ * D_;
    gemm_mainloop(g_xhi, g_xlo, D_, Bh, Bl, D_, m0, n0, D_ / 64, sb, tid, acc);

    const float* bias = (z == 0) ? bq : (z == 1) ? bk : bv;

    if (z < 2) {
        __nv_bfloat16* oh = (z == 0) ? g_qhi : g_khi;
        __nv_bfloat16* ol = (z == 0) ? g_qlo : g_klo;
        #pragma unroll
        for (int ma = 0; ma < 4; ma++) {
            int m = m0 + wm * 64 + ma * 16 + (lane >> 2);
            #pragma unroll
            for (int na = 0; na < 4; na++) {
                int n = n0 + wn * 32 + na * 8 + (lane & 3) * 2;
                float bv0 = __ldg(bias + n), bv1 = __ldg(bias + n + 1);
                __nv_bfloat16 h0, l0, h1, l1;
                split2(acc[ma][na][0] + bv0, h0, l0);
                split2(acc[ma][na][1] + bv1, h1, l1);
                *(__nv_bfloat162*)(oh + (size_t)m * D_ + n) = __nv_bfloat162(h0, h1);
                *(__nv_bfloat162*)(ol + (size_t)m * D_ + n) = __nv_bfloat162(l0, l1);
                split2(acc[ma][na][2] + bv0, h0, l0);
                split2(acc[ma][na][3] + bv1, h1, l1);
                *(__nv_bfloat162*)(oh + (size_t)(m + 8) * D_ + n) = __nv_bfloat162(h0, h1);
                *(__nv_bfloat162*)(ol + (size_t)(m + 8) * D_ + n) = __nv_bfloat162(l0, l1);
            }
        }
    } else {
        // V: stage fp32 tile in SMEM, write transposed [b][d][n]
        float* sf = (float*)dyn;   // 128 x 129 fp32 = 66048 B (stages done)
        #pragma unroll
        for (int ma = 0; ma < 4; ma++) {
            int r = wm * 64 + ma * 16 + (lane >> 2);
            #pragma unroll
            for (int na = 0; na < 4; na++) {
                int nl = wn * 32 + na * 8 + (lane & 3) * 2;
                float bv0 = __ldg(bias + n0 + nl), bv1 = __ldg(bias + n0 + nl + 1);
                sf[r * 129 + nl]           = acc[ma][na][0] + bv0;
                sf[r * 129 + nl + 1]       = acc[ma][na][1] + bv1;
                sf[(r + 8) * 129 + nl]     = acc[ma][na][2] + bv0;
                sf[(r + 8) * 129 + nl + 1] = acc[ma][na][3] + bv1;
            }
        }
        __syncthreads();
        int b = m0 >> 11;
        int mloc = m0 & 2047;
        int r = tid >> 1;
        int c0 = (tid & 1) * 64;
        __nv_bfloat16* oh = g_vthi + ((size_t)b * D_ + n0 + r) * N_ + mloc + c0;
        __nv_bfloat16* ol = g_vtlo + ((size_t)b * D_ + n0 + r) * N_ + mloc + c0;
        #pragma unroll
        for (int c = 0; c < 64; c += 2) {
            __nv_bfloat16 h0, l0, h1, l1;
            split2(sf[(c0 + c) * 129 + r], h0, l0);
            split2(sf[(c0 + c + 1) * 129 + r], h1, l1);
            *(__nv_bfloat162*)(oh + c) = __nv_bfloat162(h0, h1);
            *(__nv_bfloat162*)(ol + c) = __nv_bfloat162(l0, l1);
        }
    }
}

// ---------------------------------------------------------------------------
// colmean(V) per batch: mean[b][d] = (1/N) sum_n v[b][n][d]
// ---------------------------------------------------------------------------
__global__ __launch_bounds__(256) void colmean_kernel() {
    int gw = blockIdx.x * 8 + (threadIdx.x >> 5);
    int lane = threadIdx.x & 31;
    const __nv_bfloat162* ph = (const __nv_bfloat162*)(g_vthi + (size_t)gw * N_);
    const __nv_bfloat162* pl = (const __nv_bfloat162*)(g_vtlo + (size_t)gw * N_);
    float s = 0.f;
    for (int i = lane; i < N_ / 2; i += 32) {
        __nv_bfloat162 a = ph[i], b2 = pl[i];
        s += __bfloat162float(a.x) + __bfloat162float(a.y)
           + __bfloat162float(b2.x) + __bfloat162float(b2.y);
    }
    #pragma unroll
    for (int o = 16; o > 0; o >>= 1) s += __shfl_xor_sync(0xffffffffu, s, o);
    if (lane == 0) g_mean[gw] = s * (1.0f / N_);
}

// ---------------------------------------------------------------------------
// Scores GEMM (q.k^T) with fused max-free exp + split-bf16 numerator write +
// per-tile row-sum partials. No fp32 score array, no separate softmax pass.
// Safe: |s*scale| <= ||q|| ||k|| * scale ~ 7.5  ->  exp never overflows fp32.
// ---------------------------------------------------------------------------
__global__ __launch_bounds__(256, 1) void scores_mma_kernel(const void* __restrict__ lens) {
    const int b = blockIdx.z;
    const long long L = get_len(lens, b);
    const int Lpad = ((int)L + 127) & ~127;
    const int m0 = blockIdx.y * 128, n0 = blockIdx.x * 128;
    if (m0 >= Lpad || n0 >= Lpad) return;

    extern __shared__ char dyn[];
    uint32_t sb = smem_u32(dyn);
    const int tid = threadIdx.x, lane = tid & 31, wid = tid >> 5;
    const int wm = wid & 1, wn = wid >> 1;

    float acc[4][4][4] = {};
    const size_t off = (size_t)b * N_ * D_;
    gemm_mainloop(g_qhi + off, g_qlo + off, D_, g_khi + off, g_klo + off, D_,
                  m0, n0, D_ / 64, sb, tid, acc);

    float rsum[4][2] = {};
    #pragma unroll
    for (int ma = 0; ma < 4; ma++) {
        int q0 = m0 + wm * 64 + ma * 16 + (lane >> 2);
        #pragma unroll
        for (int na = 0; na < 4; na++) {
            int kj = n0 + wn * 32 + na * 8 + (lane & 3) * 2;
            bool k0d = (kj >= L), k1d = (kj + 1 >= L);
            #pragma unroll
            for (int h = 0; h < 2; h++) {
                int q = q0 + h * 8;
                bool qd = (q >= L);
                float e0 = (qd || k0d) ? 0.f : __expf(acc[ma][na][h * 2]     * SCALE);
                float e1 = (qd || k1d) ? 0.f : __expf(acc[ma][na][h * 2 + 1] * SCALE);
                __nv_bfloat16 h0, l0, h1, l1;
                split2(e0, h0, l0); split2(e1, h1, l1);
                size_t c = ((size_t)b * N_ + q) * N_ + kj;
                *(__nv_bfloat162*)(g_phi + c) = __nv_bfloat162(h0, h1);
                *(__nv_bfloat162*)(g_plo + c) = __nv_bfloat162(l0, l1);
                rsum[ma][h] += e0 + e1;
            }
        }
    }
    // Row-sum reduce: lanes 4t..4t+3 share a row -> shfl over low 2 bits
    __syncthreads();
    float* ps = (float*)dyn;   // [128][4]
    #pragma unroll
    for (int ma = 0; ma < 4; ma++)
        #pragma unroll
        for (int h = 0; h < 2; h++) {
            float v = rsum[ma][h];
            v += __shfl_xor_sync(0xffffffffu, v, 1);
            v += __shfl_xor_sync(0xffffffffu, v, 2);
            if ((lane & 3) == 0) {
                int r = wm * 64 + ma * 16 + (lane >> 2) + h * 8;
                ps[r * 4 + wn] = v;
            }
        }
    __syncthreads();
    if (tid < 128) {
        float s = ps[tid * 4] + ps[tid * 4 + 1] + ps[tid * 4 + 2] + ps[tid * 4 + 3];
        g_psum[((size_t)b * 16 + (n0 >> 7)) * N_ + m0 + tid] = s;
    }
}

// ---------------------------------------------------------------------------
// Row inverse-sum: rinv[b][q] = 1 / sum_t psum[b][t][q]   (0 if dead row)
// ---------------------------------------------------------------------------
__global__ __launch_bounds__(256) void rinv_kernel() {
    int idx = blockIdx.x * 256 + threadIdx.x;   // b*N + q
    int b = idx >> 11, q = idx & 2047;
    float s = 0.f;
    #pragma unroll
    for (int t = 0; t < 16; t++)
        s += g_psum[((size_t)b * 16 + t) * N_ + q];
    g_rinv[idx] = (s > 0.f) ? 1.0f / s : 0.f;
}

// ---------------------------------------------------------------------------
// Output GEMM: O = (E @ V) * rinv, live tiles only
// ---------------------------------------------------------------------------
__global__ __launch_bounds__(256, 1) void out_mma_kernel(float* __restrict__ Out,
                                                         const void* __restrict__ lens) {
    const int b = blockIdx.z;
    const long long L = get_len(lens, b);
    const int Lpad = ((int)L + 127) & ~127;
    const int m0 = blockIdx.y * 128, n0 = blockIdx.x * 128;
    if (m0 >= Lpad) return;

    extern __shared__ char dyn[];
    uint32_t sb = smem_u32(dyn);
    const int tid = threadIdx.x, lane = tid & 31, wid = tid >> 5;
    const int wm = wid & 1, wn = wid >> 1;

    float acc[4][4][4] = {};
    const size_t poff = (size_t)b * N_ * N_;
    const size_t voff = (size_t)b * D_ * N_;
    gemm_mainloop(g_phi + poff, g_plo + poff, N_, g_vthi + voff, g_vtlo + voff, N_,
                  m0, n0, Lpad / 64, sb, tid, acc);

    #pragma unroll
    for (int ma = 0; ma < 4; ma++) {
        int m = m0 + wm * 64 + ma * 16 + (lane >> 2);
        float ri0 = g_rinv[(size_t)b * N_ + m];
        float ri1 = g_rinv[(size_t)b * N_ + m + 8];
        float* r0 = Out + ((size_t)b * N_ + m) * D_;
        float* r1 = Out + ((size_t)b * N_ + m + 8) * D_;
        #pragma unroll
        for (int na = 0; na < 4; na++) {
            int n = n0 + wn * 32 + na * 8 + (lane & 3) * 2;
            *(float2*)(r0 + n) = make_float2(acc[ma][na][0] * ri0, acc[ma][na][1] * ri0);
            *(float2*)(r1 + n) = make_float2(acc[ma][na][2] * ri1, acc[ma][na][3] * ri1);
        }
    }
}

// ---------------------------------------------------------------------------
// Fill dead rows: O[b, qi>=L, :] = colmean(V)
// ---------------------------------------------------------------------------
__global__ __launch_bounds__(128) void fill_kernel(float* __restrict__ Out,
                                                   const void* __restrict__ lens) {
    const int b = blockIdx.y, qi = blockIdx.x;
    const long long L = get_len(lens, b);
    if (qi < L) return;
    float4 v = ((const float4*)(g_mean + (size_t)b * D_))[threadIdx.x];
    ((float4*)(Out + ((size_t)b * N_ + qi) * D_))[threadIdx.x] = v;
}

// ---------------------------------------------------------------------------
extern "C" void kernel_launch(void* const* d_in, const int* in_sizes, int n_in,
                              void* d_out, int out_size)
{
    const float* x    = (const float*)d_in[0];
    const void*  lens = d_in[1];
    const float* Wq   = (const float*)d_in[2];
    const float* bq   = (const float*)d_in[3];
    const float* Wk   = (const float*)d_in[4];
    const float* bk   = (const float*)d_in[5];
    const float* Wv   = (const float*)d_in[6];
    const float* bv   = (const float*)d_in[7];
    float* out = (float*)d_out;

    cudaFuncSetAttribute(qkv_mma_kernel,    cudaFuncAttributeMaxDynamicSharedMemorySize, SMEM_BYTES);
    cudaFuncSetAttribute(scores_mma_kernel, cudaFuncAttributeMaxDynamicSharedMemorySize, SMEM_BYTES);
    cudaFuncSetAttribute(out_mma_kernel,    cudaFuncAttributeMaxDynamicSharedMemorySize, SMEM_BYTES);

    convert_x_kernel<<<M_ * D_ / 4 / 256, 256>>>(x);
    convert_w_kernel<<<dim3(D_ * D_ / 4 / 256, 1, 3), 256>>>(Wq, Wk, Wv);
    qkv_mma_kernel<<<dim3(D_ / 128, M_ / 128, 3), 256, SMEM_BYTES>>>(bq, bk, bv, lens);
    colmean_kernel<<<B_ * D_ / 8, 256>>>();
    scores_mma_kernel<<<dim3(N_ / 128, N_ / 128, B_), 256, SMEM_BYTES>>>(lens);
    rinv_kernel<<<M_ / 256, 256>>>();
    out_mma_kernel<<<dim3(D_ / 128, N_ / 128, B_), 256, SMEM_BYTES>>>(out, lens);
    fill_kernel<<<dim3(N_, B_), 128>>>(out, lens);
}

// round 6
// speedup vs baseline: 5.8396x; 1.0390x over previous
#include <cuda_runtime.h>
#include <cuda_bf16.h>
#include <cstdint>

// ---------------------------------------------------------------------------
// Problem constants
// ---------------------------------------------------------------------------
constexpr int B_ = 8;
constexpr int N_ = 2048;
constexpr int D_ = 512;
constexpr int M_ = B_ * N_;                    // 16384
constexpr float SCALE = 0.04419417382415922f;  // 1/sqrt(512)

// SMEM: 3 stages x (Ahi,Alo,Bhi,Blo each 128x64 bf16 = 16KB) = 192KB
constexpr int STAGE_BYTES = 65536;
constexpr int NSTAGES = 3;
constexpr int SMEM_BYTES = NSTAGES * STAGE_BYTES;
constexpr int OFF_AL = 16384;
constexpr int OFF_BH = 32768;
constexpr int OFF_BL = 49152;

// ---------------------------------------------------------------------------
// Scratch (static __device__: allocation-guard safe; zero-initialized at load)
// ---------------------------------------------------------------------------
__device__ __align__(256) __nv_bfloat16 g_xhi[(size_t)M_ * D_];
__device__ __align__(256) __nv_bfloat16 g_xlo[(size_t)M_ * D_];
__device__ __align__(256) __nv_bfloat16 g_whi[(size_t)3 * D_ * D_];
__device__ __align__(256) __nv_bfloat16 g_wlo[(size_t)3 * D_ * D_];
__device__ __align__(256) __nv_bfloat16 g_qhi[(size_t)M_ * D_];
__device__ __align__(256) __nv_bfloat16 g_qlo[(size_t)M_ * D_];
__device__ __align__(256) __nv_bfloat16 g_khi[(size_t)M_ * D_];
__device__ __align__(256) __nv_bfloat16 g_klo[(size_t)M_ * D_];
__device__ __align__(256) __nv_bfloat16 g_vthi[(size_t)B_ * D_ * N_];  // [b][d][n]
__device__ __align__(256) __nv_bfloat16 g_vtlo[(size_t)B_ * D_ * N_];
__device__ __align__(256) __nv_bfloat16 g_phi[(size_t)B_ * N_ * N_];   // exp numerators hi
__device__ __align__(256) __nv_bfloat16 g_plo[(size_t)B_ * N_ * N_];   // exp numerators lo
__device__ __align__(256) float         g_psum[(size_t)B_ * 16 * N_];  // per-tile row sums
__device__ __align__(256) float         g_rinv[(size_t)B_ * N_];       // 1/rowsum
__device__ __align__(256) float         g_mean[(size_t)B_ * D_];       // colmean(V)

// ---------------------------------------------------------------------------
// Helpers
// ---------------------------------------------------------------------------
__device__ __forceinline__ uint32_t smem_u32(const void* p) {
    uint32_t a;
    asm("{ .reg .u64 t; cvta.to.shared.u64 t, %1; cvt.u32.u64 %0, t; }" : "=r"(a) : "l"(p));
    return a;
}
#define SW128(o) ((o) ^ (((o) >> 3) & 0x70))

#define CP16(dst, src) \
    asm volatile("cp.async.cg.shared.global [%0], [%1], 16;" :: "r"(dst), "l"(src) : "memory")
#define CP_COMMIT() asm volatile("cp.async.commit_group;" ::: "memory")
#define CP_WAIT1() asm volatile("cp.async.wait_group 1;" ::: "memory")
#define CP_WAIT0() asm volatile("cp.async.wait_group 0;" ::: "memory")

#define LDSM4(r0, r1, r2, r3, a) \
    asm volatile("ldmatrix.sync.aligned.m8n8.x4.shared.b16 {%0,%1,%2,%3}, [%4];" \
                 : "=r"(r0), "=r"(r1), "=r"(r2), "=r"(r3) : "r"(a))

#define MMA(c, a, b0, b1) \
    asm volatile("mma.sync.aligned.m16n8k16.row.col.f32.bf16.bf16.f32 " \
                 "{%0,%1,%2,%3},{%4,%5,%6,%7},{%8,%9},{%0,%1,%2,%3};" \
                 : "+f"((c)[0]), "+f"((c)[1]), "+f"((c)[2]), "+f"((c)[3]) \
                 : "r"((a)[0]), "r"((a)[1]), "r"((a)[2]), "r"((a)[3]), "r"(b0), "r"(b1))

__device__ __forceinline__ void split2(float f, __nv_bfloat16& h, __nv_bfloat16& l) {
    h = __float2bfloat16_rn(f);
    l = __float2bfloat16_rn(f - __bfloat162float(h));
}

// event_lengths dtype sniffing (int64 vs int32-demoted)
__device__ __forceinline__ long long get_len(const void* lens, int b) {
    const long long* p64 = (const long long*)lens;
    long long probe = p64[0];
    if (probe >= 1 && probe <= (long long)N_) return p64[b];
    return (long long)((const int*)lens)[b];
}

// ---------------------------------------------------------------------------
// Async stage loader: 4 tiles of 128 rows x 64 bf16 (SW128) per stage
// ---------------------------------------------------------------------------
__device__ __forceinline__ void load_stage(
    const __nv_bfloat16* __restrict__ Ah, const __nv_bfloat16* __restrict__ Al, int lda,
    const __nv_bfloat16* __restrict__ Bh, const __nv_bfloat16* __restrict__ Bl, int ldb,
    int m0, int n0, int k0, uint32_t sbase, int tid)
{
    #pragma unroll
    for (int i = 0; i < 4; i++) {
        int idx = tid + i * 256;
        int r = idx >> 3;
        int c16 = idx & 7;
        uint32_t off = SW128((uint32_t)(r * 128 + c16 * 16));
        const __nv_bfloat16* a  = Ah + (size_t)(m0 + r) * lda + k0 + c16 * 8;
        const __nv_bfloat16* al = Al + (size_t)(m0 + r) * lda + k0 + c16 * 8;
        const __nv_bfloat16* b  = Bh + (size_t)(n0 + r) * ldb + k0 + c16 * 8;
        const __nv_bfloat16* bl = Bl + (size_t)(n0 + r) * ldb + k0 + c16 * 8;
        CP16(sbase + off, a);
        CP16(sbase + OFF_AL + off, al);
        CP16(sbase + OFF_BH + off, b);
        CP16(sbase + OFF_BL + off, bl);
    }
    CP_COMMIT();
}

// ---------------------------------------------------------------------------
// Compute one 64-wide K chunk from SMEM stage into acc (split-bf16, 3 products)
// ---------------------------------------------------------------------------
__device__ __forceinline__ void compute_chunk(uint32_t sb, int wm, int wn, int lane,
                                              float acc[4][4][4])
{
    const uint32_t rA = sb + (uint32_t)(wm * 64 + (lane & 15)) * 128;
    const uint32_t rB = sb + OFF_BH + (uint32_t)(wn * 32 + (lane & 15)) * 128;
    const uint32_t xr = (uint32_t)(lane & 7) << 4;
    const uint32_t half = (uint32_t)(lane >> 4) << 4;

    #pragma unroll
    for (int ks = 0; ks < 4; ks++) {
        uint32_t c = ((uint32_t)(ks * 32) + half) ^ xr;
        uint32_t ah[4][4], al[4][4], bh[4][2], bl[4][2];
        #pragma unroll
        for (int ma = 0; ma < 4; ma++) {
            LDSM4(ah[ma][0], ah[ma][1], ah[ma][2], ah[ma][3], rA + ma * 2048 + c);
            LDSM4(al[ma][0], al[ma][1], al[ma][2], al[ma][3], rA + OFF_AL + ma * 2048 + c);
        }
        #pragma unroll
        for (int p = 0; p < 2; p++) {
            uint32_t t0, t1, t2, t3;
            LDSM4(t0, t1, t2, t3, rB + p * 2048 + c);
            bh[p * 2][0] = t0; bh[p * 2 + 1][0] = t1;
            bh[p * 2][1] = t2; bh[p * 2 + 1][1] = t3;
            LDSM4(t0, t1, t2, t3, rB + 16384 + p * 2048 + c);
            bl[p * 2][0] = t0; bl[p * 2 + 1][0] = t1;
            bl[p * 2][1] = t2; bl[p * 2 + 1][1] = t3;
        }
        #pragma unroll
        for (int ma = 0; ma < 4; ma++)
            #pragma unroll
            for (int na = 0; na < 4; na++) {
                MMA(acc[ma][na], ah[ma], bh[na][0], bh[na][1]);
                MMA(acc[ma][na], ah[ma], bl[na][0], bl[na][1]);
                MMA(acc[ma][na], al[ma], bh[na][0], bh[na][1]);
            }
    }
}

// ---------------------------------------------------------------------------
// Full GEMM mainloop, 3-stage cp.async pipeline, ONE sync per chunk:
//   wait(chunk c) -> barrier -> issue load(c+2) -> compute(c)
// The barrier proves all warps finished chunk c-1, whose stage (c+2)%3
// == (c-1)%3 the new load overwrites.
// ---------------------------------------------------------------------------
__device__ __forceinline__ void gemm_mainloop(
    const __nv_bfloat16* Ah, const __nv_bfloat16* Al, int lda,
    const __nv_bfloat16* Bh, const __nv_bfloat16* Bl, int ldb,
    int m0, int n0, int nChunks, uint32_t sb, int tid, float acc[4][4][4])
{
    const int lane = tid & 31, wid = tid >> 5;
    const int wm = wid & 1, wn = wid >> 1;

    load_stage(Ah, Al, lda, Bh, Bl, ldb, m0, n0, 0, sb, tid);
    if (nChunks > 1)
        load_stage(Ah, Al, lda, Bh, Bl, ldb, m0, n0, 64, sb + STAGE_BYTES, tid);
    for (int c = 0; c < nChunks; c++) {
        if (c + 1 < nChunks) CP_WAIT1(); else CP_WAIT0();
        __syncthreads();
        if (c + 2 < nChunks)
            load_stage(Ah, Al, lda, Bh, Bl, ldb, m0, n0, (c + 2) * 64,
                       sb + ((c + 2) % NSTAGES) * STAGE_BYTES, tid);
        compute_chunk(sb + (c % NSTAGES) * STAGE_BYTES, wm, wn, lane, acc);
    }
}

// ---------------------------------------------------------------------------
// Combined convert: x (8192 CTAs) + W q/k/v (768 CTAs)
// ---------------------------------------------------------------------------
__global__ __launch_bounds__(256) void convert_kernel(const float* __restrict__ x,
                                                      const float* __restrict__ Wq,
                                                      const float* __restrict__ Wk,
                                                      const float* __restrict__ Wv) {
    const int id = blockIdx.x;
    const float* src;
    __nv_bfloat16 *dh, *dl;
    size_t i;
    if (id < 8192) {
        src = x; dh = g_xhi; dl = g_xlo;
        i = (size_t)id * 256 + threadIdx.x;
    } else {
        int t = id - 8192;
        int z = t >> 8;
        src = (z == 0) ? Wq : (z == 1) ? Wk : Wv;
        dh = g_whi + (size_t)z * D_ * D_;
        dl = g_wlo + (size_t)z * D_ * D_;
        i = (size_t)(t & 255) * 256 + threadIdx.x;
    }
    float4 v = ((const float4*)src)[i];
    __nv_bfloat16 h0, l0, h1, l1, h2, l2, h3, l3;
    split2(v.x, h0, l0); split2(v.y, h1, l1);
    split2(v.z, h2, l2); split2(v.w, h3, l3);
    ((__nv_bfloat162*)dh)[i * 2]     = __nv_bfloat162(h0, h1);
    ((__nv_bfloat162*)dh)[i * 2 + 1] = __nv_bfloat162(h2, h3);
    ((__nv_bfloat162*)dl)[i * 2]     = __nv_bfloat162(l0, l1);
    ((__nv_bfloat162*)dl)[i * 2 + 1] = __nv_bfloat162(l2, l3);
}

// ---------------------------------------------------------------------------
// Q/K projection GEMM (z: 0=q, 1=k). Dead rows (>= Lpad) skipped.
// ---------------------------------------------------------------------------
__global__ __launch_bounds__(256, 1) void qk_mma_kernel(const float* __restrict__ bq,
                                                        const float* __restrict__ bk,
                                                        const void* __restrict__ lens) {
    extern __shared__ char dyn[];
    uint32_t sb = smem_u32(dyn);
    const int tid = threadIdx.x, lane = tid & 31, wid = tid >> 5;
    const int wm = wid & 1, wn = wid >> 1;
    const int z = blockIdx.z;
    const int m0 = blockIdx.y * 128, n0 = blockIdx.x * 128;

    const long long L = get_len(lens, m0 >> 11);
    const int Lpad = ((int)L + 127) & ~127;
    if ((m0 & 2047) >= Lpad) return;

    float acc[4][4][4] = {};
    const __nv_bfloat16* Bh = g_whi + (size_t)z * D_ * D_;
    const __nv_bfloat16* Bl = g_wlo + (size_t)z * D_ * D_;
    gemm_mainloop(g_xhi, g_xlo, D_, Bh, Bl, D_, m0, n0, D_ / 64, sb, tid, acc);

    const float* bias = (z == 0) ? bq : bk;
    __nv_bfloat16* oh = (z == 0) ? g_qhi : g_khi;
    __nv_bfloat16* ol = (z == 0) ? g_qlo : g_klo;
    #pragma unroll
    for (int ma = 0; ma < 4; ma++) {
        int m = m0 + wm * 64 + ma * 16 + (lane >> 2);
        #pragma unroll
        for (int na = 0; na < 4; na++) {
            int n = n0 + wn * 32 + na * 8 + (lane & 3) * 2;
            float bv0 = __ldg(bias + n), bv1 = __ldg(bias + n + 1);
            __nv_bfloat16 h0, l0, h1, l1;
            split2(acc[ma][na][0] + bv0, h0, l0);
            split2(acc[ma][na][1] + bv1, h1, l1);
            *(__nv_bfloat162*)(oh + (size_t)m * D_ + n) = __nv_bfloat162(h0, h1);
            *(__nv_bfloat162*)(ol + (size_t)m * D_ + n) = __nv_bfloat162(l0, l1);
            split2(acc[ma][na][2] + bv0, h0, l0);
            split2(acc[ma][na][3] + bv1, h1, l1);
            *(__nv_bfloat162*)(oh + (size_t)(m + 8) * D_ + n) = __nv_bfloat162(h0, h1);
            *(__nv_bfloat162*)(ol + (size_t)(m + 8) * D_ + n) = __nv_bfloat162(l0, l1);
        }
    }
}

// ---------------------------------------------------------------------------
// MEGA1: V projection (ids 0..511) + scores GEMM (ids 512..2559), one launch.
// V-proj and scores are independent (scores needs only q,k); sharing the grid
// lets live V CTAs backfill the slots dead scores tiles vacate instantly.
// ---------------------------------------------------------------------------
__global__ __launch_bounds__(256, 1) void mega1_kernel(const float* __restrict__ bv,
                                                       const void* __restrict__ lens) {
    extern __shared__ char dyn[];
    uint32_t sb = smem_u32(dyn);
    const int tid = threadIdx.x, lane = tid & 31, wid = tid >> 5;
    const int wm = wid & 1, wn = wid >> 1;
    const int id = blockIdx.x;

    if (id < 512) {
        // ---- V projection, output transposed [b][d][n] ----
        const int m0 = (id >> 2) * 128, n0 = (id & 3) * 128;
        float acc[4][4][4] = {};
        const __nv_bfloat16* Bh = g_whi + (size_t)2 * D_ * D_;
        const __nv_bfloat16* Bl = g_wlo + (size_t)2 * D_ * D_;
        gemm_mainloop(g_xhi, g_xlo, D_, Bh, Bl, D_, m0, n0, D_ / 64, sb, tid, acc);

        __syncthreads();             // mainloop has no trailing sync; protect SMEM reuse
        float* sf = (float*)dyn;     // 128 x 129 fp32
        #pragma unroll
        for (int ma = 0; ma < 4; ma++) {
            int r = wm * 64 + ma * 16 + (lane >> 2);
            #pragma unroll
            for (int na = 0; na < 4; na++) {
                int nl = wn * 32 + na * 8 + (lane & 3) * 2;
                float bv0 = __ldg(bv + n0 + nl), bv1 = __ldg(bv + n0 + nl + 1);
                sf[r * 129 + nl]           = acc[ma][na][0] + bv0;
                sf[r * 129 + nl + 1]       = acc[ma][na][1] + bv1;
                sf[(r + 8) * 129 + nl]     = acc[ma][na][2] + bv0;
                sf[(r + 8) * 129 + nl + 1] = acc[ma][na][3] + bv1;
            }
        }
        __syncthreads();
        int b = m0 >> 11;
        int mloc = m0 & 2047;
        int r = tid >> 1;
        int c0 = (tid & 1) * 64;
        __nv_bfloat16* oh = g_vthi + ((size_t)b * D_ + n0 + r) * N_ + mloc + c0;
        __nv_bfloat16* ol = g_vtlo + ((size_t)b * D_ + n0 + r) * N_ + mloc + c0;
        #pragma unroll
        for (int c = 0; c < 64; c += 2) {
            __nv_bfloat16 h0, l0, h1, l1;
            split2(sf[(c0 + c) * 129 + r], h0, l0);
            split2(sf[(c0 + c + 1) * 129 + r], h1, l1);
            *(__nv_bfloat162*)(oh + c) = __nv_bfloat162(h0, h1);
            *(__nv_bfloat162*)(ol + c) = __nv_bfloat162(l0, l1);
        }
        return;
    }

    // ---- scores GEMM with fused max-free exp + row-sum partials ----
    const int s = id - 512;
    const int b = s >> 8;
    const int m0 = ((s >> 4) & 15) * 128, n0 = (s & 15) * 128;
    const long long L = get_len(lens, b);
    const int Lpad = ((int)L + 127) & ~127;
    if (m0 >= Lpad || n0 >= Lpad) return;

    float acc[4][4][4] = {};
    const size_t off = (size_t)b * N_ * D_;
    gemm_mainloop(g_qhi + off, g_qlo + off, D_, g_khi + off, g_klo + off, D_,
                  m0, n0, D_ / 64, sb, tid, acc);

    float rsum[4][2] = {};
    #pragma unroll
    for (int ma = 0; ma < 4; ma++) {
        int q0 = m0 + wm * 64 + ma * 16 + (lane >> 2);
        #pragma unroll
        for (int na = 0; na < 4; na++) {
            int kj = n0 + wn * 32 + na * 8 + (lane & 3) * 2;
            bool k0d = (kj >= L), k1d = (kj + 1 >= L);
            #pragma unroll
            for (int h = 0; h < 2; h++) {
                int q = q0 + h * 8;
                bool qd = (q >= L);
                float e0 = (qd || k0d) ? 0.f : __expf(acc[ma][na][h * 2]     * SCALE);
                float e1 = (qd || k1d) ? 0.f : __expf(acc[ma][na][h * 2 + 1] * SCALE);
                __nv_bfloat16 h0, l0, h1, l1;
                split2(e0, h0, l0); split2(e1, h1, l1);
                size_t c = ((size_t)b * N_ + q) * N_ + kj;
                *(__nv_bfloat162*)(g_phi + c) = __nv_bfloat162(h0, h1);
                *(__nv_bfloat162*)(g_plo + c) = __nv_bfloat162(l0, l1);
                rsum[ma][h] += e0 + e1;
            }
        }
    }
    __syncthreads();
    float* ps = (float*)dyn;   // [128][4]
    #pragma unroll
    for (int ma = 0; ma < 4; ma++)
        #pragma unroll
        for (int h = 0; h < 2; h++) {
            float v = rsum[ma][h];
            v += __shfl_xor_sync(0xffffffffu, v, 1);
            v += __shfl_xor_sync(0xffffffffu, v, 2);
            if ((lane & 3) == 0) {
                int r = wm * 64 + ma * 16 + (lane >> 2) + h * 8;
                ps[r * 4 + wn] = v;
            }
        }
    __syncthreads();
    if (tid < 128) {
        float t = ps[tid * 4] + ps[tid * 4 + 1] + ps[tid * 4 + 2] + ps[tid * 4 + 3];
        g_psum[((size_t)b * 16 + (n0 >> 7)) * N_ + m0 + tid] = t;
    }
}

// ---------------------------------------------------------------------------
// MEGA2: rinv (ids 0..63) + colmean(V) (ids 64..575)
// Dead-tile psum entries are never written and stay zero from module init.
// ---------------------------------------------------------------------------
__global__ __launch_bounds__(256) void mega2_kernel() {
    const int id = blockIdx.x;
    if (id < 64) {
        int idx = id * 256 + threadIdx.x;   // b*N + q
        int b = idx >> 11, q = idx & 2047;
        float s = 0.f;
        #pragma unroll
        for (int t = 0; t < 16; t++)
            s += g_psum[((size_t)b * 16 + t) * N_ + q];
        g_rinv[idx] = (s > 0.f) ? 1.0f / s : 0.f;
        return;
    }
    int gw = (id - 64) * 8 + (threadIdx.x >> 5);
    int lane = threadIdx.x & 31;
    const __nv_bfloat162* ph = (const __nv_bfloat162*)(g_vthi + (size_t)gw * N_);
    const __nv_bfloat162* pl = (const __nv_bfloat162*)(g_vtlo + (size_t)gw * N_);
    float s = 0.f;
    for (int i = lane; i < N_ / 2; i += 32) {
        __nv_bfloat162 a = ph[i], b2 = pl[i];
        s += __bfloat162float(a.x) + __bfloat162float(a.y)
           + __bfloat162float(b2.x) + __bfloat162float(b2.y);
    }
    #pragma unroll
    for (int o = 16; o > 0; o >>= 1) s += __shfl_xor_sync(0xffffffffu, s, o);
    if (lane == 0) g_mean[gw] = s * (1.0f / N_);
}

// ---------------------------------------------------------------------------
// OUT+FILL: ids 0..511 = PV GEMM (stores predicated m<L); ids 512.. = fill
// dead rows with colmean(V). Disjoint row ownership -> no race in one launch.
// ---------------------------------------------------------------------------
__global__ __launch_bounds__(256, 1) void out_fill_kernel(float* __restrict__ Out,
                                                          const void* __restrict__ lens) {
    const int id = blockIdx.x;
    if (id >= 512) {
        // fill: 2 rows per CTA
        int t = id - 512;
        int b = t >> 10;
        const long long L = get_len(lens, b);
        int qi = ((t & 1023) << 1) + (threadIdx.x >> 7);
        if (qi < L) return;
        int c = threadIdx.x & 127;
        float4 v = ((const float4*)(g_mean + (size_t)b * D_))[c];
        ((float4*)(Out + ((size_t)b * N_ + qi) * D_))[c] = v;
        return;
    }

    const int b = id >> 6;
    const int rem = id & 63;
    const int m0 = (rem >> 2) * 128, n0 = (rem & 3) * 128;
    const long long L = get_len(lens, b);
    const int Lpad = ((int)L + 127) & ~127;
    if (m0 >= Lpad) return;

    extern __shared__ char dyn[];
    uint32_t sb = smem_u32(dyn);
    const int tid = threadIdx.x, lane = tid & 31, wid = tid >> 5;
    const int wm = wid & 1, wn = wid >> 1;

    float acc[4][4][4] = {};
    const size_t poff = (size_t)b * N_ * N_;
    const size_t voff = (size_t)b * D_ * N_;
    gemm_mainloop(g_phi + poff, g_plo + poff, N_, g_vthi + voff, g_vtlo + voff, N_,
                  m0, n0, Lpad / 64, sb, tid, acc);

    #pragma unroll
    for (int ma = 0; ma < 4; ma++) {
        int m = m0 + wm * 64 + ma * 16 + (lane >> 2);
        float ri0 = g_rinv[(size_t)b * N_ + m];
        float ri1 = g_rinv[(size_t)b * N_ + m + 8];
        float* r0 = Out + ((size_t)b * N_ + m) * D_;
        float* r1 = Out + ((size_t)b * N_ + m + 8) * D_;
        #pragma unroll
        for (int na = 0; na < 4; na++) {
            int n = n0 + wn * 32 + na * 8 + (lane & 3) * 2;
            if (m < L)
                *(float2*)(r0 + n) = make_float2(acc[ma][na][0] * ri0, acc[ma][na][1] * ri0);
            if (m + 8 < L)
                *(float2*)(r1 + n) = make_float2(acc[ma][na][2] * ri1, acc[ma][na][3] * ri1);
        }
    }
}

// ---------------------------------------------------------------------------
extern "C" void kernel_launch(void* const* d_in, const int* in_sizes, int n_in,
                              void* d_out, int out_size)
{
    const float* x    = (const float*)d_in[0];
    const void*  lens = d_in[1];
    const float* Wq   = (const float*)d_in[2];
    const float* bq   = (const float*)d_in[3];
    const float* Wk   = (const float*)d_in[4];
    const float* bk   = (const float*)d_in[5];
    const float* Wv   = (const float*)d_in[6];
    const float* bv   = (const float*)d_in[7];
    float* out = (float*)d_out;

    cudaFuncSetAttribute(qk_mma_kernel,   cudaFuncAttributeMaxDynamicSharedMemorySize, SMEM_BYTES);
    cudaFuncSetAttribute(mega1_kernel,    cudaFuncAttributeMaxDynamicSharedMemorySize, SMEM_BYTES);
    cudaFuncSetAttribute(out_fill_kernel, cudaFuncAttributeMaxDynamicSharedMemorySize, SMEM_BYTES);

    convert_kernel<<<8960, 256>>>(x, Wq, Wk, Wv);
    qk_mma_kernel<<<dim3(D_ / 128, M_ / 128, 2), 256, SMEM_BYTES>>>(bq, bk, lens);
    mega1_kernel<<<512 + 2048, 256, SMEM_BYTES>>>(bv, lens);
    mega2_kernel<<<64 + 512, 256>>>();
    out_fill_kernel<<<512 + 8192, 256, SMEM_BYTES>>>(out, lens);
}